// round 12
// baseline (speedup 1.0000x reference)
#include <cuda_runtime.h>
#include <math.h>

#define N_NODES 50000
#define N_EDGES 800000
#define F_IN    128
#define F_H     16
#define F_OUT   300
#define MAXDEG  64   // P(Poisson(16) > 64) ~ 1e-20; padded CSR row width

// ---------------- device scratch (no allocations allowed) ----------------
__device__ float g_dinv[N_NODES];
__device__ int   g_cursor[N_NODES];            // per-node fill cursor == degree
__device__ int   g_eidx[N_NODES * MAXDEG];     // padded CSR: src lists grouped by dst
__device__ float g_t  [N_NODES * F_H];         // pre-agg features, PRE-SCALED by dinv[src]
__device__ float g_l  [N_NODES * F_H];         // skip-linear features
__device__ float g_agg[N_NODES * F_H];         // aggregation result

// ---------------- f32x2 packed helpers ----------------
__device__ __forceinline__ unsigned long long pack2(float lo, float hi) {
    unsigned long long r;
    asm("mov.b64 %0, {%1, %2};" : "=l"(r) : "f"(lo), "f"(hi));
    return r;
}
__device__ __forceinline__ float2 unpack2(unsigned long long v) {
    float2 r;
    asm("mov.b64 {%0, %1}, %2;" : "=f"(r.x), "=f"(r.y) : "l"(v));
    return r;
}
__device__ __forceinline__ void ffma2(unsigned long long& d,
                                      unsigned long long a, unsigned long long b) {
    asm("fma.rn.f32x2 %0, %1, %2, %0;" : "+l"(d) : "l"(a), "l"(b));
}

// ---------------- padded-CSR build ----------------
__global__ void k_zero() {
    int n = blockIdx.x * blockDim.x + threadIdx.x;
    if (n < N_NODES) g_cursor[n] = 0;
}

// 4 edges/thread, both index streams via int4
__global__ void k_fill(const int* __restrict__ ei) {
    int t = blockIdx.x * blockDim.x + threadIdx.x;
    if (t >= N_EDGES / 4) return;
    int4 s4 = __ldg(reinterpret_cast<const int4*>(ei) + t);
    int4 d4 = __ldg(reinterpret_cast<const int4*>(ei + N_EDGES) + t);
    int p;
    p = atomicAdd(&g_cursor[d4.x], 1); if (p < MAXDEG) g_eidx[d4.x * MAXDEG + p] = s4.x;
    p = atomicAdd(&g_cursor[d4.y], 1); if (p < MAXDEG) g_eidx[d4.y * MAXDEG + p] = s4.y;
    p = atomicAdd(&g_cursor[d4.z], 1); if (p < MAXDEG) g_eidx[d4.z * MAXDEG + p] = s4.z;
    p = atomicAdd(&g_cursor[d4.w], 1); if (p < MAXDEG) g_eidx[d4.w * MAXDEG + p] = s4.w;
}

__global__ void k_dinv() {
    int n = blockIdx.x * blockDim.x + threadIdx.x;
    if (n < N_NODES) g_dinv[n] = rsqrtf((float)g_cursor[n] + 1.0f);
}

// ---------------- layer-1 GEMM: register-tiled, f32x2 over node pairs ----------------
// Block: 256 threads, 256-node tile, 32 output cols (16 W1 -> t, 16 Wl1 -> l).
// Thread: 8 nodes (4 f32x2 pairs) x 4 cols. K staged in chunks of 8.
// x read from DRAM exactly once; weights pre-duplicated (w,w) in shared.
__global__ __launch_bounds__(256) void k_gemm1(const float* __restrict__ x,
                                               const float* __restrict__ W1,
                                               const float* __restrict__ Wl1) {
    __shared__ float sX[8][256];                        // 8 KB: one K-chunk, node-major
    __shared__ unsigned long long sWd[F_IN][32];        // 32 KB: (w,w) duplicated pairs

    int tid = threadIdx.x;
    // stage duplicated weights: sWd[k][0..15]=W1[k][:], [16..31]=Wl1[k][:]
    for (int i = tid; i < F_IN * 32; i += 256) {
        int k = i >> 5, col = i & 31;
        float v = (col < 16) ? W1[k * 16 + col] : Wl1[k * 16 + (col - 16)];
        sWd[k][col] = pack2(v, v);
    }

    int base = blockIdx.x * 256;
    int ng   = tid >> 3;   // node group: 8 nodes starting at ng*8
    int cg   = tid & 7;    // col group:  4 cols  starting at cg*4

    unsigned long long acc[16];   // [np*4 + c], np=node pair 0..3, c=col 0..3
#pragma unroll
    for (int q = 0; q < 16; q++) acc[q] = 0ULL;

    const float4* x4 = reinterpret_cast<const float4*>(x);

    for (int chunk = 0; chunk < 16; chunk++) {
        __syncthreads();
        {   // stage this thread's node row: 8 consecutive k values
            int node = base + tid;
            float4 a = make_float4(0.f, 0.f, 0.f, 0.f);
            float4 b = a;
            if (node < N_NODES) {
                a = __ldg(x4 + (size_t)node * 32 + chunk * 2);
                b = __ldg(x4 + (size_t)node * 32 + chunk * 2 + 1);
            }
            sX[0][tid] = a.x; sX[1][tid] = a.y; sX[2][tid] = a.z; sX[3][tid] = a.w;
            sX[4][tid] = b.x; sX[5][tid] = b.y; sX[6][tid] = b.z; sX[7][tid] = b.w;
        }
        __syncthreads();

#pragma unroll
        for (int kk = 0; kk < 8; kk++) {
            int kg = chunk * 8 + kk;
            const ulonglong2* xp =
                reinterpret_cast<const ulonglong2*>(&sX[kk][ng * 8]);
            ulonglong2 xa = xp[0], xb = xp[1];  // node pairs (0,1)(2,3)(4,5)(6,7)
            const ulonglong2* wp =
                reinterpret_cast<const ulonglong2*>(&sWd[kg][cg * 4]);
            ulonglong2 wa = wp[0], wb = wp[1];  // cols cg*4 .. cg*4+3 (dup pairs)

            ffma2(acc[0],  xa.x, wa.x); ffma2(acc[1],  xa.x, wa.y);
            ffma2(acc[2],  xa.x, wb.x); ffma2(acc[3],  xa.x, wb.y);
            ffma2(acc[4],  xa.y, wa.x); ffma2(acc[5],  xa.y, wa.y);
            ffma2(acc[6],  xa.y, wb.x); ffma2(acc[7],  xa.y, wb.y);
            ffma2(acc[8],  xb.x, wa.x); ffma2(acc[9],  xb.x, wa.y);
            ffma2(acc[10], xb.x, wb.x); ffma2(acc[11], xb.x, wb.y);
            ffma2(acc[12], xb.y, wa.x); ffma2(acc[13], xb.y, wa.y);
            ffma2(acc[14], xb.y, wb.x); ffma2(acc[15], xb.y, wb.y);
        }
    }

    // epilogue: cg<4 -> t (dinv-scaled), cg>=4 -> l
#pragma unroll
    for (int np = 0; np < 4; np++) {
        float2 p0 = unpack2(acc[np * 4 + 0]);
        float2 p1 = unpack2(acc[np * 4 + 1]);
        float2 p2 = unpack2(acc[np * 4 + 2]);
        float2 p3 = unpack2(acc[np * 4 + 3]);
        int n0 = base + ng * 8 + 2 * np;
        int n1 = n0 + 1;
        if (cg < 4) {
            int co = cg * 4;
            if (n0 < N_NODES) {
                float d = g_dinv[n0];
                *reinterpret_cast<float4*>(g_t + (size_t)n0 * F_H + co) =
                    make_float4(d * p0.x, d * p1.x, d * p2.x, d * p3.x);
            }
            if (n1 < N_NODES) {
                float d = g_dinv[n1];
                *reinterpret_cast<float4*>(g_t + (size_t)n1 * F_H + co) =
                    make_float4(d * p0.y, d * p1.y, d * p2.y, d * p3.y);
            }
        } else {
            int co = (cg - 4) * 4;
            if (n0 < N_NODES)
                *reinterpret_cast<float4*>(g_l + (size_t)n0 * F_H + co) =
                    make_float4(p0.x, p1.x, p2.x, p3.x);
            if (n1 < N_NODES)
                *reinterpret_cast<float4*>(g_l + (size_t)n1 * F_H + co) =
                    make_float4(p0.y, p1.y, p2.y, p3.y);
        }
    }
}

// ---------------- padded-CSR gather: agg[n] = t[n] + sum_{s->n} t[s] ----------------
// 4 threads per node, each owns one float4 column chunk; int4 index loads.
__global__ __launch_bounds__(256) void k_gather() {
    int idx  = blockIdx.x * 256 + threadIdx.x;
    int n    = idx >> 2;
    int part = idx & 3;
    if (n >= N_NODES) return;

    const float4* tb = reinterpret_cast<const float4*>(g_t);
    float4 acc = __ldg(tb + (size_t)n * 4 + part);   // self term

    int deg = g_cursor[n];
    if (deg > MAXDEG) deg = MAXDEG;
    const int4* row4 = reinterpret_cast<const int4*>(g_eidx + n * MAXDEG);

    int e = 0;
    for (; e + 4 <= deg; e += 4) {
        int4 s4 = __ldg(row4 + (e >> 2));
        float4 v0 = __ldg(tb + (size_t)s4.x * 4 + part);
        float4 v1 = __ldg(tb + (size_t)s4.y * 4 + part);
        float4 v2 = __ldg(tb + (size_t)s4.z * 4 + part);
        float4 v3 = __ldg(tb + (size_t)s4.w * 4 + part);
        acc.x += v0.x; acc.y += v0.y; acc.z += v0.z; acc.w += v0.w;
        acc.x += v1.x; acc.y += v1.y; acc.z += v1.z; acc.w += v1.w;
        acc.x += v2.x; acc.y += v2.y; acc.z += v2.z; acc.w += v2.w;
        acc.x += v3.x; acc.y += v3.y; acc.z += v3.z; acc.w += v3.w;
    }
    if (e < deg) {
        int4 s4 = __ldg(row4 + (e >> 2));
        int rem = deg - e;
        int ss[4] = {s4.x, s4.y, s4.z, s4.w};
        for (int r = 0; r < rem; r++) {
            float4 v = __ldg(tb + (size_t)ss[r] * 4 + part);
            acc.x += v.x; acc.y += v.y; acc.z += v.z; acc.w += v.w;
        }
    }
    reinterpret_cast<float4*>(g_agg)[(size_t)n * 4 + part] = acc;
}

// ---------------- layer-2 GEMM fused with layer-1 finalize ----------------
// h1 = relu(dinv*agg + b1) + l + bl1 ; t = dinv*(h1@W2) ; l = h1@Wl2
__global__ __launch_bounds__(256) void k_gemm2(const float* __restrict__ W2,
                                               const float* __restrict__ Wl2,
                                               const float* __restrict__ b1,
                                               const float* __restrict__ bl1) {
    __shared__ float sW[F_H][32];
    __shared__ float sb1[F_H], sbl1[F_H];
    int tid = threadIdx.x;
    if (tid < F_H * F_H) {
        int k = tid / F_H, j = tid % F_H;
        sW[k][j]      = W2[tid];
        sW[k][j + 16] = Wl2[tid];
    }
    if (tid < F_H) { sb1[tid] = b1[tid]; sbl1[tid] = bl1[tid]; }
    __syncthreads();

    int n = blockIdx.x * 256 + tid;
    if (n >= N_NODES) return;

    float dv = g_dinv[n];
    const float4* ag4 = reinterpret_cast<const float4*>(g_agg + (size_t)n * F_H);
    const float4* ll4 = reinterpret_cast<const float4*>(g_l   + (size_t)n * F_H);
    float h[16];
#pragma unroll
    for (int q = 0; q < 4; q++) {
        float4 a = ag4[q];
        float4 l = ll4[q];
        h[4*q+0] = fmaxf(dv * a.x + sb1[4*q+0], 0.f) + l.x + sbl1[4*q+0];
        h[4*q+1] = fmaxf(dv * a.y + sb1[4*q+1], 0.f) + l.y + sbl1[4*q+1];
        h[4*q+2] = fmaxf(dv * a.z + sb1[4*q+2], 0.f) + l.z + sbl1[4*q+2];
        h[4*q+3] = fmaxf(dv * a.w + sb1[4*q+3], 0.f) + l.w + sbl1[4*q+3];
    }

    unsigned long long acc[16];
#pragma unroll
    for (int q = 0; q < 16; q++) acc[q] = 0ULL;
#pragma unroll
    for (int k = 0; k < F_H; k++) {
        unsigned long long hk = pack2(h[k], h[k]);
        const ulonglong2* wp = reinterpret_cast<const ulonglong2*>(&sW[k][0]);
#pragma unroll
        for (int q = 0; q < 8; q++) {
            ulonglong2 w = wp[q];
            ffma2(acc[2*q],   hk, w.x);
            ffma2(acc[2*q+1], hk, w.y);
        }
    }
    float o[32];
#pragma unroll
    for (int q = 0; q < 16; q++) {
        float2 p = unpack2(acc[q]);
        o[2*q] = p.x; o[2*q+1] = p.y;
    }
    float4* tp = reinterpret_cast<float4*>(g_t + (size_t)n * F_H);
    float4* lp = reinterpret_cast<float4*>(g_l + (size_t)n * F_H);
#pragma unroll
    for (int q = 0; q < 4; q++) {
        tp[q] = make_float4(dv * o[4*q], dv * o[4*q+1], dv * o[4*q+2], dv * o[4*q+3]);
        lp[q] = make_float4(o[16+4*q], o[16+4*q+1], o[16+4*q+2], o[16+4*q+3]);
    }
}

// ---------------- layer-2 finalize: t = dinv*(relu(dinv*agg+b2)+l+bl2) ----------------
__global__ __launch_bounds__(256) void k_prep3(const float* __restrict__ b2,
                                               const float* __restrict__ bl2) {
    int n = blockIdx.x * blockDim.x + threadIdx.x;
    if (n >= N_NODES) return;
    float dv = g_dinv[n];
    const float4* ag4 = reinterpret_cast<const float4*>(g_agg + (size_t)n * F_H);
    const float4* ll4 = reinterpret_cast<const float4*>(g_l   + (size_t)n * F_H);
    float4* tp = reinterpret_cast<float4*>(g_t + (size_t)n * F_H);
#pragma unroll
    for (int q = 0; q < 4; q++) {
        float4 a = ag4[q];
        float4 l = ll4[q];
        float4 h;
        h.x = dv * (fmaxf(dv * a.x + __ldg(b2 + 4*q+0), 0.f) + l.x + __ldg(bl2 + 4*q+0));
        h.y = dv * (fmaxf(dv * a.y + __ldg(b2 + 4*q+1), 0.f) + l.y + __ldg(bl2 + 4*q+1));
        h.z = dv * (fmaxf(dv * a.z + __ldg(b2 + 4*q+2), 0.f) + l.z + __ldg(bl2 + 4*q+2));
        h.w = dv * (fmaxf(dv * a.w + __ldg(b2 + 4*q+3), 0.f) + l.w + __ldg(bl2 + 4*q+3));
        tp[q] = h;
    }
}

// ---------------- output: out = log_softmax(dinv*agg @ Wo + bo) ----------------
// 128 nodes per block (16 per warp) -> Wo staged once per 128 nodes
#define WT_STRIDE 20
__global__ __launch_bounds__(256) void k_out(const float* __restrict__ Wo,
                                             const float* __restrict__ bo,
                                             float* __restrict__ out) {
    __shared__ float sWt[F_OUT * WT_STRIDE];  // sWt[c*20 + k] = Wo[k][c]
    __shared__ float sbo[F_OUT];

    int tid = threadIdx.x;
    for (int i = tid; i < F_H * F_OUT; i += 256) {
        int k = i / F_OUT, c = i % F_OUT;
        sWt[c * WT_STRIDE + k] = Wo[i];
    }
    for (int c = tid; c < F_OUT; c += 256) sbo[c] = bo[c];
    __syncthreads();

    int w    = tid >> 5;
    int lane = tid & 31;

    for (int nn = 0; nn < 16; nn++) {
        int n = blockIdx.x * 128 + w * 16 + nn;
        if (n >= N_NODES) return;

        float dv = g_dinv[n];
        const float4* ag = reinterpret_cast<const float4*>(g_agg + (size_t)n * F_H);
        unsigned long long A2[8];
#pragma unroll
        for (int q = 0; q < 4; q++) {
            float4 a = __ldg(ag + q);
            A2[2*q]   = pack2(dv * a.x, dv * a.y);
            A2[2*q+1] = pack2(dv * a.z, dv * a.w);
        }

        float v[10];
        float m = -INFINITY;
#pragma unroll
        for (int i = 0; i < 10; i++) {
            int c = lane + 32 * i;
            if (c < F_OUT) {
                const ulonglong2* wp =
                    reinterpret_cast<const ulonglong2*>(&sWt[c * WT_STRIDE]);
                ulonglong2 w01 = wp[0], w23 = wp[1], w45 = wp[2], w67 = wp[3];
                unsigned long long acc = 0ULL;
                ffma2(acc, A2[0], w01.x); ffma2(acc, A2[1], w01.y);
                ffma2(acc, A2[2], w23.x); ffma2(acc, A2[3], w23.y);
                ffma2(acc, A2[4], w45.x); ffma2(acc, A2[5], w45.y);
                ffma2(acc, A2[6], w67.x); ffma2(acc, A2[7], w67.y);
                float2 p = unpack2(acc);
                float s = sbo[c] + p.x + p.y;
                v[i] = s;
                m = fmaxf(m, s);
            }
        }
#pragma unroll
        for (int off = 16; off; off >>= 1)
            m = fmaxf(m, __shfl_xor_sync(0xFFFFFFFF, m, off));
        float sum = 0.f;
#pragma unroll
        for (int i = 0; i < 10; i++) {
            int c = lane + 32 * i;
            if (c < F_OUT) sum += __expf(v[i] - m);
        }
#pragma unroll
        for (int off = 16; off; off >>= 1)
            sum += __shfl_xor_sync(0xFFFFFFFF, sum, off);
        float lse = m + logf(sum);

        float* orow = out + (size_t)n * F_OUT;
#pragma unroll
        for (int i = 0; i < 10; i++) {
            int c = lane + 32 * i;
            if (c < F_OUT) orow[c] = v[i] - lse;
        }
    }
}

// ---------------- launch ----------------
extern "C" void kernel_launch(void* const* d_in, const int* in_sizes, int n_in,
                              void* d_out, int out_size) {
    const float* x   = (const float*)d_in[0];
    const int*   ei  = (const int*)  d_in[1];
    const float* W1  = (const float*)d_in[2];
    const float* b1  = (const float*)d_in[3];
    const float* Wl1 = (const float*)d_in[4];
    const float* bl1 = (const float*)d_in[5];
    const float* W2  = (const float*)d_in[6];
    const float* b2  = (const float*)d_in[7];
    const float* Wl2 = (const float*)d_in[8];
    const float* bl2 = (const float*)d_in[9];
    const float* Wo  = (const float*)d_in[10];
    const float* bo  = (const float*)d_in[11];
    float* out = (float*)d_out;

    const int GN = (N_NODES + 255) / 256;           // 196
    const int G4 = (N_EDGES / 4 + 255) / 256;       // 782
    const int GG = (N_NODES * 4 + 255) / 256;       // 782

    // padded-CSR build + norms
    k_zero<<<GN, 256>>>();
    k_fill<<<G4, 256>>>(ei);
    k_dinv<<<GN, 256>>>();

    // layer 1 (tiled GEMM: 256 nodes/block)
    k_gemm1 <<<GN, 256>>>(x, W1, Wl1);
    k_gather<<<GG, 256>>>();

    // layer 2
    k_gemm2 <<<GN, 256>>>(W2, Wl2, b1, bl1);
    k_gather<<<GG, 256>>>();

    // output conv
    k_prep3 <<<GN, 256>>>(b2, bl2);
    k_gather<<<GG, 256>>>();

    k_out<<<(N_NODES + 127) / 128, 256>>>(Wo, bo, out);
}

// round 13
// speedup vs baseline: 1.1632x; 1.1632x over previous
#include <cuda_runtime.h>
#include <math.h>

#define N_NODES 50000
#define N_EDGES 800000
#define F_IN    128
#define F_H     16
#define F_OUT   300
#define MAXDEG  64   // P(Poisson(16) > 64) ~ 1e-20; padded CSR row width

// ---------------- device scratch (no allocations allowed) ----------------
__device__ float g_dinv[N_NODES];
__device__ int   g_cursor[N_NODES];            // per-node fill cursor == degree
__device__ int   g_eidx[N_NODES * MAXDEG];     // padded CSR: src lists grouped by dst
__device__ float g_t  [N_NODES * F_H];         // gather source table
__device__ float g_l  [N_NODES * F_H];         // skip-linear features
__device__ float g_agg[N_NODES * F_H];         // gather destination / h buffer

// ---------------- f32x2 packed helpers ----------------
__device__ __forceinline__ unsigned long long pack2(float lo, float hi) {
    unsigned long long r;
    asm("mov.b64 %0, {%1, %2};" : "=l"(r) : "f"(lo), "f"(hi));
    return r;
}
__device__ __forceinline__ float2 unpack2(unsigned long long v) {
    float2 r;
    asm("mov.b64 {%0, %1}, %2;" : "=f"(r.x), "=f"(r.y) : "l"(v));
    return r;
}
__device__ __forceinline__ void ffma2(unsigned long long& d,
                                      unsigned long long a, unsigned long long b) {
    asm("fma.rn.f32x2 %0, %1, %2, %0;" : "+l"(d) : "l"(a), "l"(b));
}

// ---------------- padded-CSR build ----------------
__global__ void k_zero() {
    int n = blockIdx.x * blockDim.x + threadIdx.x;
    if (n < N_NODES) g_cursor[n] = 0;
}

// 4 edges/thread, both index streams via int4
__global__ void k_fill(const int* __restrict__ ei) {
    int t = blockIdx.x * blockDim.x + threadIdx.x;
    if (t >= N_EDGES / 4) return;
    int4 s4 = __ldg(reinterpret_cast<const int4*>(ei) + t);
    int4 d4 = __ldg(reinterpret_cast<const int4*>(ei + N_EDGES) + t);
    int p;
    p = atomicAdd(&g_cursor[d4.x], 1); if (p < MAXDEG) g_eidx[d4.x * MAXDEG + p] = s4.x;
    p = atomicAdd(&g_cursor[d4.y], 1); if (p < MAXDEG) g_eidx[d4.y * MAXDEG + p] = s4.y;
    p = atomicAdd(&g_cursor[d4.z], 1); if (p < MAXDEG) g_eidx[d4.z * MAXDEG + p] = s4.z;
    p = atomicAdd(&g_cursor[d4.w], 1); if (p < MAXDEG) g_eidx[d4.w * MAXDEG + p] = s4.w;
}

__global__ void k_dinv() {
    int n = blockIdx.x * blockDim.x + threadIdx.x;
    if (n < N_NODES) g_dinv[n] = rsqrtf((float)g_cursor[n] + 1.0f);
}

// ---------------- layer-1 GEMM (f32x2): t = dinv*(x@W1), l = x@Wl1 ----------------
// R9 champion: 2 threads/node: part0 -> W1 (t), part1 -> Wl1 (l); 16 outputs each.
__global__ __launch_bounds__(256) void k_gemm1(const float* __restrict__ x,
                                               const float* __restrict__ W1,
                                               const float* __restrict__ Wl1) {
    __shared__ float sW[F_IN][32];   // [k][0..15]=W1 row k, [k][16..31]=Wl1 row k
    int tid = threadIdx.x;
    for (int i = tid; i < F_IN * F_H; i += 256) {
        int k = i / F_H, j = i % F_H;
        sW[k][j]      = W1[i];
        sW[k][j + 16] = Wl1[i];
    }
    __syncthreads();

    int idx  = blockIdx.x * 256 + tid;
    int n    = idx >> 1;
    int part = idx & 1;
    if (n >= N_NODES) return;

    unsigned long long acc[8];
#pragma unroll
    for (int q = 0; q < 8; q++) acc[q] = 0ULL;

    const float4* xr = reinterpret_cast<const float4*>(x + (size_t)n * F_IN);
    const int co = part * 16;

#pragma unroll 4
    for (int k4 = 0; k4 < F_IN / 4; k4++) {
        float4 xv = __ldg(xr + k4);
        float xs[4] = {xv.x, xv.y, xv.z, xv.w};
#pragma unroll
        for (int s = 0; s < 4; s++) {
            unsigned long long xx = pack2(xs[s], xs[s]);
            const ulonglong2* wp =
                reinterpret_cast<const ulonglong2*>(&sW[k4 * 4 + s][co]);
            ulonglong2 w01 = wp[0], w23 = wp[1], w45 = wp[2], w67 = wp[3];
            ffma2(acc[0], xx, w01.x); ffma2(acc[1], xx, w01.y);
            ffma2(acc[2], xx, w23.x); ffma2(acc[3], xx, w23.y);
            ffma2(acc[4], xx, w45.x); ffma2(acc[5], xx, w45.y);
            ffma2(acc[6], xx, w67.x); ffma2(acc[7], xx, w67.y);
        }
    }

    float o[16];
#pragma unroll
    for (int q = 0; q < 8; q++) {
        float2 p = unpack2(acc[q]);
        o[2 * q]     = p.x;
        o[2 * q + 1] = p.y;
    }

    if (part == 0) {
        float dv = g_dinv[n];
        float4* tp = reinterpret_cast<float4*>(g_t + (size_t)n * F_H);
#pragma unroll
        for (int q = 0; q < 4; q++)
            tp[q] = make_float4(dv * o[4*q], dv * o[4*q+1], dv * o[4*q+2], dv * o[4*q+3]);
    } else {
        float4* lp = reinterpret_cast<float4*>(g_l + (size_t)n * F_H);
#pragma unroll
        for (int q = 0; q < 4; q++)
            lp[q] = make_float4(o[4*q], o[4*q+1], o[4*q+2], o[4*q+3]);
    }
}

// ---------------- fused gather + elementwise finalize ----------------
// acc = src[n] + sum_{s->n} src[s]   (4 threads/node, one float4 chunk each)
// mode 0: src=g_t,   dst=g_agg, dst = relu(dv*acc + b[c]) + l[c] + bl[c]      (h1)
// mode 1: src=g_t,   dst=g_agg, dst = dv*(relu(dv*acc + b[c]) + l[c] + bl[c]) (t3)
// mode 2: src=g_agg, dst=g_t,   dst = dv*acc                                  (final)
__global__ __launch_bounds__(256) void k_gather(int mode,
                                                const float* __restrict__ b,
                                                const float* __restrict__ bl) {
    int idx  = blockIdx.x * 256 + threadIdx.x;
    int n    = idx >> 2;
    int part = idx & 3;
    if (n >= N_NODES) return;

    const float4* tb = reinterpret_cast<const float4*>(mode == 2 ? g_agg : g_t);
    float4 acc = __ldg(tb + (size_t)n * 4 + part);   // self term

    int deg = g_cursor[n];
    if (deg > MAXDEG) deg = MAXDEG;
    const int4* row4 = reinterpret_cast<const int4*>(g_eidx + n * MAXDEG);

    int e = 0;
    for (; e + 4 <= deg; e += 4) {
        int4 s4 = __ldg(row4 + (e >> 2));
        float4 v0 = __ldg(tb + (size_t)s4.x * 4 + part);
        float4 v1 = __ldg(tb + (size_t)s4.y * 4 + part);
        float4 v2 = __ldg(tb + (size_t)s4.z * 4 + part);
        float4 v3 = __ldg(tb + (size_t)s4.w * 4 + part);
        acc.x += v0.x; acc.y += v0.y; acc.z += v0.z; acc.w += v0.w;
        acc.x += v1.x; acc.y += v1.y; acc.z += v1.z; acc.w += v1.w;
        acc.x += v2.x; acc.y += v2.y; acc.z += v2.z; acc.w += v2.w;
        acc.x += v3.x; acc.y += v3.y; acc.z += v3.z; acc.w += v3.w;
    }
    if (e < deg) {
        int4 s4 = __ldg(row4 + (e >> 2));
        int rem = deg - e;
        int ss[4] = {s4.x, s4.y, s4.z, s4.w};
        for (int r = 0; r < rem; r++) {
            float4 v = __ldg(tb + (size_t)ss[r] * 4 + part);
            acc.x += v.x; acc.y += v.y; acc.z += v.z; acc.w += v.w;
        }
    }

    float dv = g_dinv[n];
    float4 outv;
    if (mode == 2) {
        outv = make_float4(dv * acc.x, dv * acc.y, dv * acc.z, dv * acc.w);
        reinterpret_cast<float4*>(g_t)[(size_t)n * 4 + part] = outv;
        return;
    }
    float4 bb  = __ldg(reinterpret_cast<const float4*>(b)  + part);
    float4 bbl = __ldg(reinterpret_cast<const float4*>(bl) + part);
    float4 lv  = reinterpret_cast<const float4*>(g_l)[(size_t)n * 4 + part];
    outv.x = fmaxf(dv * acc.x + bb.x, 0.f) + lv.x + bbl.x;
    outv.y = fmaxf(dv * acc.y + bb.y, 0.f) + lv.y + bbl.y;
    outv.z = fmaxf(dv * acc.z + bb.z, 0.f) + lv.z + bbl.z;
    outv.w = fmaxf(dv * acc.w + bb.w, 0.f) + lv.w + bbl.w;
    if (mode == 1) {
        outv.x *= dv; outv.y *= dv; outv.z *= dv; outv.w *= dv;
    }
    reinterpret_cast<float4*>(g_agg)[(size_t)n * 4 + part] = outv;
}

// ---------------- layer-2 GEMM: reads h1 from g_agg; t = dinv*(h@W2), l = h@Wl2 ----
__global__ __launch_bounds__(256) void k_gemm2(const float* __restrict__ W2,
                                               const float* __restrict__ Wl2) {
    __shared__ float sW[F_H][32];
    int tid = threadIdx.x;
    if (tid < F_H * F_H) {
        int k = tid / F_H, j = tid % F_H;
        sW[k][j]      = W2[tid];
        sW[k][j + 16] = Wl2[tid];
    }
    __syncthreads();

    int n = blockIdx.x * 256 + tid;
    if (n >= N_NODES) return;

    float dv = g_dinv[n];
    const float4* hg = reinterpret_cast<const float4*>(g_agg + (size_t)n * F_H);
    float h[16];
#pragma unroll
    for (int q = 0; q < 4; q++) {
        float4 a = hg[q];
        h[4*q+0] = a.x; h[4*q+1] = a.y; h[4*q+2] = a.z; h[4*q+3] = a.w;
    }

    unsigned long long acc[16];
#pragma unroll
    for (int q = 0; q < 16; q++) acc[q] = 0ULL;
#pragma unroll
    for (int k = 0; k < F_H; k++) {
        unsigned long long hk = pack2(h[k], h[k]);
        const ulonglong2* wp = reinterpret_cast<const ulonglong2*>(&sW[k][0]);
#pragma unroll
        for (int q = 0; q < 8; q++) {
            ulonglong2 w = wp[q];
            ffma2(acc[2*q],   hk, w.x);
            ffma2(acc[2*q+1], hk, w.y);
        }
    }
    float o[32];
#pragma unroll
    for (int q = 0; q < 16; q++) {
        float2 p = unpack2(acc[q]);
        o[2*q] = p.x; o[2*q+1] = p.y;
    }
    float4* tp = reinterpret_cast<float4*>(g_t + (size_t)n * F_H);
    float4* lp = reinterpret_cast<float4*>(g_l + (size_t)n * F_H);
#pragma unroll
    for (int q = 0; q < 4; q++) {
        tp[q] = make_float4(dv * o[4*q], dv * o[4*q+1], dv * o[4*q+2], dv * o[4*q+3]);
        lp[q] = make_float4(o[16+4*q], o[16+4*q+1], o[16+4*q+2], o[16+4*q+3]);
    }
}

// ---------------- output: out = log_softmax(g_t @ Wo + bo)  (g_t pre-scaled) -------
// 128 nodes per block (16 per warp) -> Wo staged once per 128 nodes
#define WT_STRIDE 20
__global__ __launch_bounds__(256) void k_out(const float* __restrict__ Wo,
                                             const float* __restrict__ bo,
                                             float* __restrict__ out) {
    __shared__ float sWt[F_OUT * WT_STRIDE];  // sWt[c*20 + k] = Wo[k][c]
    __shared__ float sbo[F_OUT];

    int tid = threadIdx.x;
    for (int i = tid; i < F_H * F_OUT; i += 256) {
        int k = i / F_OUT, c = i % F_OUT;
        sWt[c * WT_STRIDE + k] = Wo[i];
    }
    for (int c = tid; c < F_OUT; c += 256) sbo[c] = bo[c];
    __syncthreads();

    int w    = tid >> 5;
    int lane = tid & 31;

    for (int nn = 0; nn < 16; nn++) {
        int n = blockIdx.x * 128 + w * 16 + nn;
        if (n >= N_NODES) return;

        const float4* ag = reinterpret_cast<const float4*>(g_t + (size_t)n * F_H);
        unsigned long long A2[8];
#pragma unroll
        for (int q = 0; q < 4; q++) {
            float4 a = __ldg(ag + q);
            A2[2*q]   = pack2(a.x, a.y);
            A2[2*q+1] = pack2(a.z, a.w);
        }

        float v[10];
        float m = -INFINITY;
#pragma unroll
        for (int i = 0; i < 10; i++) {
            int c = lane + 32 * i;
            if (c < F_OUT) {
                const ulonglong2* wp =
                    reinterpret_cast<const ulonglong2*>(&sWt[c * WT_STRIDE]);
                ulonglong2 w01 = wp[0], w23 = wp[1], w45 = wp[2], w67 = wp[3];
                unsigned long long acc = 0ULL;
                ffma2(acc, A2[0], w01.x); ffma2(acc, A2[1], w01.y);
                ffma2(acc, A2[2], w23.x); ffma2(acc, A2[3], w23.y);
                ffma2(acc, A2[4], w45.x); ffma2(acc, A2[5], w45.y);
                ffma2(acc, A2[6], w67.x); ffma2(acc, A2[7], w67.y);
                float2 p = unpack2(acc);
                float s = sbo[c] + p.x + p.y;
                v[i] = s;
                m = fmaxf(m, s);
            }
        }
#pragma unroll
        for (int off = 16; off; off >>= 1)
            m = fmaxf(m, __shfl_xor_sync(0xFFFFFFFF, m, off));
        float sum = 0.f;
#pragma unroll
        for (int i = 0; i < 10; i++) {
            int c = lane + 32 * i;
            if (c < F_OUT) sum += __expf(v[i] - m);
        }
#pragma unroll
        for (int off = 16; off; off >>= 1)
            sum += __shfl_xor_sync(0xFFFFFFFF, sum, off);
        float lse = m + logf(sum);

        float* orow = out + (size_t)n * F_OUT;
#pragma unroll
        for (int i = 0; i < 10; i++) {
            int c = lane + 32 * i;
            if (c < F_OUT) orow[c] = v[i] - lse;
        }
    }
}

// ---------------- launch ----------------
extern "C" void kernel_launch(void* const* d_in, const int* in_sizes, int n_in,
                              void* d_out, int out_size) {
    const float* x   = (const float*)d_in[0];
    const int*   ei  = (const int*)  d_in[1];
    const float* W1  = (const float*)d_in[2];
    const float* b1  = (const float*)d_in[3];
    const float* Wl1 = (const float*)d_in[4];
    const float* bl1 = (const float*)d_in[5];
    const float* W2  = (const float*)d_in[6];
    const float* b2  = (const float*)d_in[7];
    const float* Wl2 = (const float*)d_in[8];
    const float* bl2 = (const float*)d_in[9];
    const float* Wo  = (const float*)d_in[10];
    const float* bo  = (const float*)d_in[11];
    float* out = (float*)d_out;

    const int GN = (N_NODES + 255) / 256;           // 196
    const int G4 = (N_EDGES / 4 + 255) / 256;       // 782
    const int GG = (N_NODES * 4 + 255) / 256;       // 782
    const int G1 = (N_NODES * 2 + 255) / 256;       // 391

    // padded-CSR build + norms
    k_zero<<<GN, 256>>>();
    k_fill<<<G4, 256>>>(ei);
    k_dinv<<<GN, 256>>>();

    // layer 1
    k_gemm1 <<<G1, 256>>>(x, W1, Wl1);
    k_gather<<<GG, 256>>>(0, b1, bl1);   // -> h1 in g_agg

    // layer 2
    k_gemm2 <<<GN, 256>>>(W2, Wl2);
    k_gather<<<GG, 256>>>(1, b2, bl2);   // -> t3 in g_agg

    // output conv aggregation (src=g_agg, dst=g_t, scaled)
    k_gather<<<GG, 256>>>(2, b2, bl2);

    k_out<<<(N_NODES + 127) / 128, 256>>>(Wo, bo, out);
}